// round 3
// baseline (speedup 1.0000x reference)
#include <cuda_runtime.h>
#include <math.h>

#define MAXDIM 1024
#define NT 1024

// Scratch (device globals; no allocation allowed)
__device__ float g_Dm[MAXDIM * MAXDIM];   // symmetric merged-distance matrix (MAXD on diag/dead)
__device__ float g_Cm[MAXDIM * MAXDIM];   // cross-energy sums C[i][j] = sum W over Li x Lj (both orders)
__device__ float g_vals[MAXDIM];
__device__ int   g_idx[MAXDIM];
__device__ unsigned g_msim;               // flip-encoded max(X)
__device__ unsigned g_mabs;               // flip-encoded max|X|

__device__ __forceinline__ unsigned fflip(float f) {
    unsigned u = __float_as_uint(f);
    return (u & 0x80000000u) ? ~u : (u | 0x80000000u);
}
__device__ __forceinline__ float funflip(unsigned u) {
    return __uint_as_float((u & 0x80000000u) ? (u & 0x7FFFFFFFu) : ~u);
}

__global__ void k_reset() { g_msim = 0u; g_mabs = 0u; }

__global__ void k_maxred(const float* __restrict__ X, int n) {
    float mx = -3.402823466e38f, ma = 0.f;
    for (int i = blockIdx.x * blockDim.x + threadIdx.x; i < n; i += gridDim.x * blockDim.x) {
        float x = X[i];
        mx = fmaxf(mx, x);
        ma = fmaxf(ma, fabsf(x));
    }
    #pragma unroll
    for (int o = 16; o; o >>= 1) {
        mx = fmaxf(mx, __shfl_down_sync(~0u, mx, o));
        ma = fmaxf(ma, __shfl_down_sync(~0u, ma, o));
    }
    __shared__ float smx[8], sma[8];
    int w = threadIdx.x >> 5, l = threadIdx.x & 31;
    if (l == 0) { smx[w] = mx; sma[w] = ma; }
    __syncthreads();
    if (threadIdx.x == 0) {
        int nw = blockDim.x >> 5;
        for (int i = 1; i < nw; i++) { mx = fmaxf(mx, smx[i]); ma = fmaxf(ma, sma[i]); }
        atomicMax(&g_msim, fflip(mx));
        atomicMax(&g_mabs, fflip(ma));
    }
}

// One block per row r: build Dsym row, C row, R row (identity), and initial (rowmin, argmin)
__global__ void k_init(const float* __restrict__ X, const float* __restrict__ W,
                       float* __restrict__ R, int D) {
    int r = blockIdx.x;
    float msim = funflip(g_msim);
    float MAXD = __fmul_rn(funflip(g_mabs), 1000.0f);
    float bv = MAXD; int bbi = 0;
    for (int k = threadIdx.x; k < D; k += blockDim.x) {
        float x = X[(size_t)r * D + k];
        float d = (k == r) ? MAXD : __fsub_rn(msim, x);
        g_Dm[(size_t)r * D + k] = d;
        g_Cm[(size_t)r * D + k] = __fadd_rn(W[(size_t)r * D + k], W[(size_t)k * D + r]);
        R[(size_t)r * D + k] = (k == r) ? 1.0f : 0.0f;
        float c = (k > r) ? d : MAXD;   // reference: lower triangle + diag are MAXD
        if (c < bv) { bv = c; bbi = k; }  // ascending k -> leftmost kept
    }
    #pragma unroll
    for (int o = 16; o; o >>= 1) {
        float ov = __shfl_down_sync(~0u, bv, o);
        int oi = __shfl_down_sync(~0u, bbi, o);
        if (ov < bv || (ov == bv && oi < bbi)) { bv = ov; bbi = oi; }
    }
    __shared__ float spv[8]; __shared__ int spi[8];
    int w = threadIdx.x >> 5, l = threadIdx.x & 31;
    if (l == 0) { spv[w] = bv; spi[w] = bbi; }
    __syncthreads();
    if (threadIdx.x == 0) {
        int nw = blockDim.x >> 5;
        for (int i = 1; i < nw; i++)
            if (spv[i] < bv || (spv[i] == bv && spi[i] < bbi)) { bv = spv[i]; bbi = spi[i]; }
        g_vals[r] = bv;
        g_idx[r] = bbi;
    }
}

// Persistent single-block HAC: 1023 sequential merges with incremental NN maintenance.
__global__ void __launch_bounds__(NT, 1) k_hac(float* __restrict__ R, int D) {
    __shared__ float s_vals[NT];
    __shared__ int   s_idx[NT];
    __shared__ int   s_alive[NT];
    __shared__ float s_cs[NT];
    __shared__ float s_within[NT];
    __shared__ float s_energy[NT];
    __shared__ int   s_member[NT];
    __shared__ int   s_list[NT];
    __shared__ float s_pv[32];
    __shared__ int   s_pi[32];
    __shared__ int s_m1, s_m2, s_nresc, s_cnt, s_take;
    __shared__ float s_cs1, s_cs2, s_ncs;

    const int j = threadIdx.x;
    const int wid = j >> 5, lane = j & 31;
    const float MAXD = __fmul_rn(funflip(g_mabs), 1000.0f);

    if (j < D) {
        s_vals[j] = g_vals[j]; s_idx[j] = g_idx[j];
        s_alive[j] = 1; s_cs[j] = 1.0f;
        s_within[j] = 0.f; s_energy[j] = 0.f;
        s_member[j] = j;
    } else {
        s_vals[j] = MAXD; s_idx[j] = 0; s_alive[j] = 0;
    }
    __syncthreads();

    for (int it = 0; it < D - 1; ++it) {
        // ---- A: global argmin over values (leftmost tie) + sequencer bookkeeping
        float v = s_vals[j]; int bi = j;
        #pragma unroll
        for (int o = 16; o; o >>= 1) {
            float ov = __shfl_down_sync(~0u, v, o);
            int oi = __shfl_down_sync(~0u, bi, o);
            if (ov < v || (ov == v && oi < bi)) { v = ov; bi = oi; }
        }
        if (lane == 0) { s_pv[wid] = v; s_pi[wid] = bi; }
        __syncthreads();
        if (j == 0) {
            float bv = s_pv[0]; int b = s_pi[0];
            #pragma unroll
            for (int w = 1; w < 32; w++) {
                float wv = s_pv[w]; int wi = s_pi[w];
                if (wv < bv || (wv == bv && wi < b)) { bv = wv; b = wi; }
            }
            int m1 = b;
            int m2 = s_idx[m1];
            s_m1 = m1; s_m2 = m2;
            float cs1 = s_cs[m1], cs2 = s_cs[m2];
            s_cs1 = cs1; s_cs2 = cs2;
            float ncs = __fadd_rn(cs1, cs2);
            s_ncs = ncs;
            s_cs[m1] = ncs;
            s_alive[m2] = 0;
            s_vals[m2] = MAXD;
            s_nresc = 0; s_cnt = 0;
        }
        __syncthreads();
        const int m1 = s_m1, m2 = s_m2;
        const float cs1 = s_cs1, cs2 = s_cs2, ncs = s_ncs;

        // ---- B: merged distances + C update + incremental (min, argmin) maintenance
        if (j < D) {
            float d1 = g_Dm[(size_t)m1 * D + j];
            float d2 = g_Dm[(size_t)m2 * D + j];
            float c1 = g_Cm[(size_t)m1 * D + j];
            float c2 = g_Cm[(size_t)m2 * D + j];
            int alv = s_alive[j];
            float nv = MAXD;
            if (alv && j != m1)
                nv = __fdiv_rn(__fadd_rn(__fmul_rn(d1, cs1), __fmul_rn(d2, cs2)), ncs);
            g_Dm[(size_t)m1 * D + j] = nv;
            g_Dm[(size_t)j * D + m1] = nv;
            float cc = __fadd_rn(c1, c2);
            g_Cm[(size_t)m1 * D + j] = cc;
            g_Cm[(size_t)j * D + m1] = cc;
            if (s_member[j] == m2) s_member[j] = m1;
            if (j == m2) {
                // cut decision (c1 == old C[m1][m2], loaded before any overwrite)
                float me = __fadd_rn(__fadd_rn(s_within[m1], s_within[m2]), c1);
                float es = __fadd_rn(s_energy[m1], s_energy[m2]);
                int take = (me >= es) ? 1 : 0;
                s_take = take;
                s_within[m1] = me;
                s_energy[m1] = take ? me : es;
            }
            int need = 0;
            if (alv && j != m1) {
                float vold = s_vals[j];
                int iold = s_idx[j];
                if (iold == m2) need = 1;            // old min removed -> rescan
                else if (m1 > j) {                   // col m1 in my active range
                    if (iold == m1) {
                        if (nv <= vold) s_vals[j] = nv;  // still leftmost-argmin at m1
                        else need = 1;                   // min got worse -> rescan
                    } else {
                        if (nv < vold) { s_vals[j] = nv; s_idx[j] = m1; }
                        else if (nv == vold && m1 < iold) s_idx[j] = m1; // leftmost tie
                    }
                }
            }
            if (j == m1) need = 1;                   // merged row: full rescan
            if (need) { int p = atomicAdd(&s_nresc, 1); s_list[p] = j; }
        }
        __syncthreads();

        // ---- C: rescans, one warp per row (up to 32 concurrent)
        int n = s_nresc;
        for (int t = wid; t < n; t += 32) {
            int r = s_list[t];
            const float* row = &g_Dm[(size_t)r * D];
            float bv = MAXD; int bbi = 0;
            for (int k = lane; k < D; k += 32) {
                float vv = MAXD;
                if (k > r && s_alive[k]) vv = row[k];
                if (vv < bv) { bv = vv; bbi = k; }
            }
            #pragma unroll
            for (int o = 16; o; o >>= 1) {
                float ov = __shfl_down_sync(~0u, bv, o);
                int oi = __shfl_down_sync(~0u, bbi, o);
                if (ov < bv || (ov == bv && oi < bbi)) { bv = ov; bbi = oi; }
            }
            if (lane == 0) { s_vals[r] = bv; s_idx[r] = bbi; }
        }
        __syncthreads();

        // ---- E: if take, mark R on leafset x leafset
        if (s_take) {
            if (j < D && s_member[j] == m1) { int p = atomicAdd(&s_cnt, 1); s_list[p] = j; }
            __syncthreads();
            int cnt = s_cnt;
            for (int ai = 0; ai < cnt; ai++) {
                float* rp = R + (size_t)s_list[ai] * D;
                for (int b = j; b < cnt; b += NT) rp[s_list[b]] = 1.0f;
            }
            // next-iteration A syncs protect s_list / s_cnt reuse
        }
    }
}

extern "C" void kernel_launch(void* const* d_in, const int* in_sizes, int n_in,
                              void* d_out, int out_size) {
    const float* X = (const float*)d_in[0];
    const float* W = (const float*)d_in[1];
    float* R = (float*)d_out;
    int n = in_sizes[0];
    int D = (int)(sqrt((double)n) + 0.5);
    if (D < 2 || D > MAXDIM) return;

    k_reset<<<1, 1>>>();
    k_maxred<<<256, 256>>>(X, n);
    k_init<<<D, 256>>>(X, W, R, D);
    k_hac<<<1, NT>>>(R, D);
}

// round 4
// speedup vs baseline: 2.3814x; 2.3814x over previous
#include <cuda_runtime.h>
#include <math.h>

#define MAXDIM 1024
#define NT 1024

// Scratch (device globals; no allocation allowed)
__device__ float g_Dm[MAXDIM * MAXDIM];   // symmetric merged-distance matrix
__device__ float g_vals[MAXDIM];
__device__ int   g_idx[MAXDIM];
__device__ unsigned g_msim;               // flip-encoded max(X)
__device__ unsigned g_mabs;               // flip-encoded max|X|

__device__ __forceinline__ unsigned fflip(float f) {
    unsigned u = __float_as_uint(f);
    return (u & 0x80000000u) ? ~u : (u | 0x80000000u);
}
__device__ __forceinline__ float funflip(unsigned u) {
    return __uint_as_float((u & 0x80000000u) ? (u & 0x7FFFFFFFu) : ~u);
}

__global__ void k_reset() { g_msim = 0u; g_mabs = 0u; }

__global__ void k_maxred(const float* __restrict__ X, int n) {
    float mx = -3.402823466e38f, ma = 0.f;
    for (int i = blockIdx.x * blockDim.x + threadIdx.x; i < n; i += gridDim.x * blockDim.x) {
        float x = X[i];
        mx = fmaxf(mx, x);
        ma = fmaxf(ma, fabsf(x));
    }
    #pragma unroll
    for (int o = 16; o; o >>= 1) {
        mx = fmaxf(mx, __shfl_down_sync(~0u, mx, o));
        ma = fmaxf(ma, __shfl_down_sync(~0u, ma, o));
    }
    __shared__ float smx[8], sma[8];
    int w = threadIdx.x >> 5, l = threadIdx.x & 31;
    if (l == 0) { smx[w] = mx; sma[w] = ma; }
    __syncthreads();
    if (threadIdx.x == 0) {
        int nw = blockDim.x >> 5;
        for (int i = 1; i < nw; i++) { mx = fmaxf(mx, smx[i]); ma = fmaxf(ma, sma[i]); }
        atomicMax(&g_msim, fflip(mx));
        atomicMax(&g_mabs, fflip(ma));
    }
}

// One block per row r: build Dsym row, R row (identity), and initial (rowmin, argmin)
__global__ void k_init(const float* __restrict__ X, float* __restrict__ R, int D) {
    int r = blockIdx.x;
    float msim = funflip(g_msim);
    float MAXD = __fmul_rn(funflip(g_mabs), 1000.0f);
    float bv = MAXD; int bbi = 0;
    for (int k = threadIdx.x; k < D; k += blockDim.x) {
        float x = X[(size_t)r * D + k];
        float d = (k == r) ? MAXD : __fsub_rn(msim, x);
        g_Dm[(size_t)r * D + k] = d;
        R[(size_t)r * D + k] = (k == r) ? 1.0f : 0.0f;
        float c = (k > r) ? d : MAXD;   // reference: lower triangle + diag are MAXD
        if (c < bv) { bv = c; bbi = k; }  // ascending k -> leftmost kept
    }
    #pragma unroll
    for (int o = 16; o; o >>= 1) {
        float ov = __shfl_down_sync(~0u, bv, o);
        int oi = __shfl_down_sync(~0u, bbi, o);
        if (ov < bv || (ov == bv && oi < bbi)) { bv = ov; bbi = oi; }
    }
    __shared__ float spv[8]; __shared__ int spi[8];
    int w = threadIdx.x >> 5, l = threadIdx.x & 31;
    if (l == 0) { spv[w] = bv; spi[w] = bbi; }
    __syncthreads();
    if (threadIdx.x == 0) {
        int nw = blockDim.x >> 5;
        for (int i = 1; i < nw; i++)
            if (spv[i] < bv || (spv[i] == bv && spi[i] < bbi)) { bv = spv[i]; bbi = spi[i]; }
        g_vals[r] = bv;
        g_idx[r] = bbi;
    }
}

// Persistent single-block HAC: sequential merges, incremental NN maintenance,
// on-demand cross-energy via leaf-pair enumeration over W (triu, so W[lo][hi]).
__global__ void __launch_bounds__(NT, 1) k_hac(const float* __restrict__ W,
                                               float* __restrict__ R, int D) {
    __shared__ float s_vals[NT];
    __shared__ int   s_idx[NT];
    __shared__ float s_cs[NT];
    __shared__ float s_within[NT];
    __shared__ float s_energy[NT];
    __shared__ int   s_member[NT];
    __shared__ int   s_list[NT];     // listA grows from 0, listB grows from NT-1 down
    __shared__ int   s_rlist[NT];    // rescan row list
    __shared__ unsigned s_amask[MAXDIM / 32];
    __shared__ float s_pv[32];
    __shared__ int   s_pi[32];
    __shared__ float s_pw[32];
    __shared__ int   s_wcA[32], s_wcB[32];
    __shared__ int s_m1, s_m2, s_take, s_nresc;
    __shared__ float s_cs1, s_cs2, s_ncs;

    const int j = threadIdx.x;
    const int wid = j >> 5, lane = j & 31;
    const unsigned lml = (1u << lane) - 1u;
    const float MAXD = __fmul_rn(funflip(g_mabs), 1000.0f);
    const bool vec_ok = ((D & 3) == 0);

    if (j < D) {
        s_vals[j] = g_vals[j]; s_idx[j] = g_idx[j];
        s_cs[j] = 1.0f; s_within[j] = 0.f; s_energy[j] = 0.f;
        s_member[j] = j;
    } else { s_vals[j] = MAXD; s_idx[j] = 0; s_member[j] = -1; }
    if (j < MAXDIM / 32) {
        int lo = j * 32;
        unsigned m = 0u;
        if (D >= lo + 32) m = 0xFFFFFFFFu;
        else if (D > lo) m = (1u << (D - lo)) - 1u;
        s_amask[j] = m;
    }
    __syncthreads();

    for (int it = 0; it < D - 1; ++it) {
        // ---- A: global argmin over values (leftmost tie)
        {
            float v = s_vals[j]; int bi = j;
            #pragma unroll
            for (int o = 16; o; o >>= 1) {
                float ov = __shfl_down_sync(~0u, v, o);
                int oi = __shfl_down_sync(~0u, bi, o);
                if (ov < v || (ov == v && oi < bi)) { v = ov; bi = oi; }
            }
            if (lane == 0) { s_pv[wid] = v; s_pi[wid] = bi; }
        }
        __syncthreads();
        if (wid == 0) {
            float v = s_pv[lane]; int bi = s_pi[lane];
            #pragma unroll
            for (int o = 16; o; o >>= 1) {
                float ov = __shfl_down_sync(~0u, v, o);
                int oi = __shfl_down_sync(~0u, bi, o);
                if (ov < v || (ov == v && oi < bi)) { v = ov; bi = oi; }
            }
            if (lane == 0) {
                int m1 = bi, m2 = s_idx[bi];
                s_m1 = m1; s_m2 = m2;
                float c1 = s_cs[m1], c2 = s_cs[m2];
                float ncs = __fadd_rn(c1, c2);
                s_cs1 = c1; s_cs2 = c2; s_ncs = ncs;
                s_cs[m1] = ncs;
                s_vals[m2] = MAXD;
                s_amask[m2 >> 5] &= ~(1u << (m2 & 31));
                s_nresc = 0;
            }
        }
        __syncthreads();
        const int m1 = s_m1, m2 = s_m2;
        const float cs1 = s_cs1, cs2 = s_cs2, ncs = s_ncs;

        // ---- Phase 1: merged distances (alive only) + incremental min maintenance
        //      + membership ballots for stable leaf-list compaction
        int mem = (j < D) ? s_member[j] : -1;
        unsigned mA = __ballot_sync(~0u, mem == m1);
        unsigned mB = __ballot_sync(~0u, mem == m2);
        if (lane == 0) { s_wcA[wid] = __popc(mA); s_wcB[wid] = __popc(mB); }
        if (mem == m2) s_member[j] = m1;
        {
            int alive = (j < D) && ((s_amask[j >> 5] >> (j & 31)) & 1);
            if (alive) {
                float nv = MAXD;
                int need = 0;
                if (j != m1) {
                    float d1 = g_Dm[(size_t)m1 * D + j];
                    float d2 = g_Dm[(size_t)m2 * D + j];
                    nv = __fdiv_rn(__fadd_rn(__fmul_rn(d1, cs1), __fmul_rn(d2, cs2)), ncs);
                    float vold = s_vals[j]; int iold = s_idx[j];
                    if (iold == m2) need = 1;                 // old min removed
                    else if (m1 > j) {                        // col m1 in my active range
                        if (iold == m1) {
                            if (nv <= vold) s_vals[j] = nv;   // still leftmost at m1
                            else need = 1;                    // min got worse
                        } else {
                            if (nv < vold) { s_vals[j] = nv; s_idx[j] = m1; }
                            else if (nv == vold && m1 < iold) s_idx[j] = m1; // leftmost tie
                        }
                    }
                } else need = 1;                              // merged row: full rescan
                g_Dm[(size_t)m1 * D + j] = nv;
                g_Dm[(size_t)j * D + m1] = nv;
                if (need) { int p = atomicAdd(&s_nresc, 1); s_rlist[p] = j; }
            }
        }
        __syncthreads();

        // ---- Phase 2a: warp-redundant prefix scan -> stable list writes; then rescans
        int cntA, cntB;
        {
            int ca = s_wcA[lane], cb = s_wcB[lane];
            #pragma unroll
            for (int o = 1; o < 32; o <<= 1) {
                int t = __shfl_up_sync(~0u, ca, o); if (lane >= o) ca += t;
                t = __shfl_up_sync(~0u, cb, o); if (lane >= o) cb += t;
            }
            cntA = __shfl_sync(~0u, ca, 31);
            cntB = __shfl_sync(~0u, cb, 31);
            int offA = __shfl_sync(~0u, ca, wid) - s_wcA[wid];
            int offB = __shfl_sync(~0u, cb, wid) - s_wcB[wid];
            if (mem == m1) s_list[offA + __popc(mA & lml)] = j;
            if (mem == m2) s_list[NT - 1 - (offB + __popc(mB & lml))] = j;
        }
        {
            int nr = s_nresc;
            for (int t = wid; t < nr; t += 32) {
                int r = s_rlist[t];
                float bv = MAXD; int bbi = 0;
                if (vec_ok) {
                    const float4* row4 = reinterpret_cast<const float4*>(&g_Dm[(size_t)r * D]);
                    float4 q[8];
                    #pragma unroll
                    for (int c = 0; c < 8; c++) {
                        int k = c * 128 + lane * 4;
                        if (k < D) q[c] = row4[k >> 2];
                        else { q[c].x = MAXD; q[c].y = MAXD; q[c].z = MAXD; q[c].w = MAXD; }
                    }
                    #pragma unroll
                    for (int c = 0; c < 8; c++) {
                        int k = c * 128 + lane * 4;
                        unsigned am = (k < D) ? (s_amask[k >> 5] >> (k & 31)) : 0u;
                        float e0 = ((am & 1u) && k > r)       ? q[c].x : MAXD;
                        float e1 = ((am & 2u) && (k + 1) > r) ? q[c].y : MAXD;
                        float e2 = ((am & 4u) && (k + 2) > r) ? q[c].z : MAXD;
                        float e3 = ((am & 8u) && (k + 3) > r) ? q[c].w : MAXD;
                        if (e0 < bv) { bv = e0; bbi = k; }
                        if (e1 < bv) { bv = e1; bbi = k + 1; }
                        if (e2 < bv) { bv = e2; bbi = k + 2; }
                        if (e3 < bv) { bv = e3; bbi = k + 3; }
                    }
                } else {
                    const float* row = &g_Dm[(size_t)r * D];
                    for (int k = lane; k < D; k += 32) {
                        int alv = (s_amask[k >> 5] >> (k & 31)) & 1;
                        float vv = (alv && k > r) ? row[k] : MAXD;
                        if (vv < bv) { bv = vv; bbi = k; }
                    }
                }
                #pragma unroll
                for (int o = 16; o; o >>= 1) {
                    float ov = __shfl_down_sync(~0u, bv, o);
                    int oi = __shfl_down_sync(~0u, bbi, o);
                    if (ov < bv || (ov == bv && oi < bbi)) { bv = ov; bbi = oi; }
                }
                if (lane == 0) { s_vals[r] = bv; s_idx[r] = bbi; }
            }
        }
        __syncthreads();

        // ---- Phase 2b: cross-energy over leaf pairs (W is triu(1): lower half exact 0)
        {
            float ps = 0.f;
            int P = cntA * cntB;
            for (int t = j; t < P; t += NT) {
                int ia = t / cntB; int ib = t - ia * cntB;
                int a = s_list[ia]; int b = s_list[NT - 1 - ib];
                int lo = a < b ? a : b, hi = a < b ? b : a;
                ps = __fadd_rn(ps, __ldg(&W[(size_t)lo * D + hi]));
            }
            #pragma unroll
            for (int o = 16; o; o >>= 1) ps = __fadd_rn(ps, __shfl_down_sync(~0u, ps, o));
            if (lane == 0) s_pw[wid] = ps;
        }
        __syncthreads();

        // ---- Phase 3: take decision (fixed reduction order -> deterministic)
        if (j == 0) {
            float cross = 0.f;
            #pragma unroll
            for (int w = 0; w < 32; w++) cross = __fadd_rn(cross, s_pw[w]);
            float me = __fadd_rn(__fadd_rn(s_within[m1], s_within[m2]), cross);
            float es = __fadd_rn(s_energy[m1], s_energy[m2]);
            int take = (me >= es) ? 1 : 0;
            s_take = take;
            s_within[m1] = me;
            s_energy[m1] = take ? me : es;
        }
        __syncthreads();

        // ---- Phase 4: if take, mark R over (L1 u L2) x (L1 u L2)
        if (s_take) {
            int cnt = cntA + cntB;
            int tot = cnt * cnt;
            for (int t = j; t < tot; t += NT) {
                int ai = t / cnt, bi2 = t - ai * cnt;
                int a = (ai < cntA) ? s_list[ai] : s_list[NT - 1 - (ai - cntA)];
                int b = (bi2 < cntA) ? s_list[bi2] : s_list[NT - 1 - (bi2 - cntA)];
                R[(size_t)a * D + b] = 1.0f;
            }
        }
        // next iteration's A-phase barriers protect s_list / s_rlist reuse
    }
}

extern "C" void kernel_launch(void* const* d_in, const int* in_sizes, int n_in,
                              void* d_out, int out_size) {
    const float* X = (const float*)d_in[0];
    const float* W = (const float*)d_in[1];
    float* R = (float*)d_out;
    int n = in_sizes[0];
    int D = (int)(sqrt((double)n) + 0.5);
    if (D < 2 || D > MAXDIM) return;

    k_reset<<<1, 1>>>();
    k_maxred<<<256, 256>>>(X, n);
    k_init<<<D, 256>>>(X, R, D);
    k_hac<<<1, NT>>>(W, R, D);
}

// round 7
// speedup vs baseline: 2.4786x; 1.0408x over previous
#include <cuda_runtime.h>
#include <math.h>

#define MAXDIM 1024
#define NT 512

// Scratch (device globals; no allocation allowed)
__device__ float g_Dm[MAXDIM * MAXDIM];   // symmetric merged-distance matrix
__device__ float g_vals[MAXDIM];
__device__ int   g_idx[MAXDIM];
__device__ unsigned g_msim;               // flip-encoded max(X)
__device__ unsigned g_mabs;               // flip-encoded max|X|

__device__ __forceinline__ unsigned fflip(float f) {
    unsigned u = __float_as_uint(f);
    return (u & 0x80000000u) ? ~u : (u | 0x80000000u);
}
__device__ __forceinline__ float funflip(unsigned u) {
    return __uint_as_float((u & 0x80000000u) ? (u & 0x7FFFFFFFu) : ~u);
}

__global__ void k_reset() { g_msim = 0u; g_mabs = 0u; }

__global__ void k_maxred(const float* __restrict__ X, int n) {
    float mx = -3.402823466e38f, ma = 0.f;
    for (int i = blockIdx.x * blockDim.x + threadIdx.x; i < n; i += gridDim.x * blockDim.x) {
        float x = X[i];
        mx = fmaxf(mx, x);
        ma = fmaxf(ma, fabsf(x));
    }
    #pragma unroll
    for (int o = 16; o; o >>= 1) {
        mx = fmaxf(mx, __shfl_down_sync(~0u, mx, o));
        ma = fmaxf(ma, __shfl_down_sync(~0u, ma, o));
    }
    __shared__ float smx[8], sma[8];
    int w = threadIdx.x >> 5, l = threadIdx.x & 31;
    if (l == 0) { smx[w] = mx; sma[w] = ma; }
    __syncthreads();
    if (threadIdx.x == 0) {
        int nw = blockDim.x >> 5;
        for (int i = 1; i < nw; i++) { mx = fmaxf(mx, smx[i]); ma = fmaxf(ma, sma[i]); }
        atomicMax(&g_msim, fflip(mx));
        atomicMax(&g_mabs, fflip(ma));
    }
}

// One block per row r: build Dsym row, R row (identity), initial (rowmin, argmin)
__global__ void k_init(const float* __restrict__ X, float* __restrict__ R, int D) {
    int r = blockIdx.x;
    float msim = funflip(g_msim);
    float MAXD = __fmul_rn(funflip(g_mabs), 1000.0f);
    float bv = MAXD; int bbi = 0;
    for (int k = threadIdx.x; k < D; k += blockDim.x) {
        float x = X[(size_t)r * D + k];
        float d = (k == r) ? MAXD : __fsub_rn(msim, x);
        g_Dm[(size_t)r * D + k] = d;
        R[(size_t)r * D + k] = (k == r) ? 1.0f : 0.0f;
        float c = (k > r) ? d : MAXD;
        if (c < bv) { bv = c; bbi = k; }  // ascending k -> leftmost kept
    }
    #pragma unroll
    for (int o = 16; o; o >>= 1) {
        float ov = __shfl_down_sync(~0u, bv, o);
        int oi = __shfl_down_sync(~0u, bbi, o);
        if (ov < bv || (ov == bv && oi < bbi)) { bv = ov; bbi = oi; }
    }
    __shared__ float spv[8]; __shared__ int spi[8];
    int w = threadIdx.x >> 5, l = threadIdx.x & 31;
    if (l == 0) { spv[w] = bv; spi[w] = bbi; }
    __syncthreads();
    if (threadIdx.x == 0) {
        int nw = blockDim.x >> 5;
        for (int i = 1; i < nw; i++)
            if (spv[i] < bv || (spv[i] == bv && spi[i] < bbi)) { bv = spv[i]; bbi = spi[i]; }
        g_vals[r] = bv;
        g_idx[r] = bbi;
    }
}

// Persistent single-block HAC, software-pipelined: 4 barriers/iter,
// R-writes overlap next distance loads, argmin pre-reduce overlaps cross-sum.
__global__ void __launch_bounds__(NT, 1) k_hac(const float* __restrict__ W,
                                               float* __restrict__ R, int D) {
    __shared__ float s_vals[MAXDIM];
    __shared__ int   s_idx[MAXDIM];
    __shared__ float s_cs[MAXDIM];
    __shared__ float s_within[MAXDIM];
    __shared__ float s_energy[MAXDIM];
    __shared__ int   s_member[MAXDIM];
    __shared__ int   s_list[MAXDIM];   // A grows from 0, B grows from MAXDIM-1 down
    __shared__ int   s_rlist[MAXDIM];
    __shared__ unsigned s_amask[MAXDIM / 32];
    __shared__ float s_pv[16];
    __shared__ int   s_pi[16];
    __shared__ float s_pw[16];
    __shared__ int   s_wcA[16], s_wcB[16];
    __shared__ int s_m1, s_m2, s_take, s_nresc;
    __shared__ float s_cs1, s_cs2, s_ncs;

    const int j = threadIdx.x;
    const int wid = j >> 5, lane = j & 31;
    const unsigned lml = (1u << lane) - 1u;
    const float MAXD = __fmul_rn(funflip(g_mabs), 1000.0f);
    const int e0 = 2 * j, e1 = 2 * j + 1;
    const bool evenD = ((D & 1) == 0);
    const bool vec4 = ((D & 3) == 0);

    for (int k = j; k < MAXDIM; k += NT) {
        if (k < D) {
            s_vals[k] = g_vals[k]; s_idx[k] = g_idx[k];
            s_cs[k] = 1.0f; s_within[k] = 0.f; s_energy[k] = 0.f;
            s_member[k] = k;
        } else { s_vals[k] = MAXD; s_idx[k] = 0; s_member[k] = -1; }
    }
    if (j < MAXDIM / 32) {
        int lo = j * 32; unsigned m = 0u;
        if (D >= lo + 32) m = 0xFFFFFFFFu;
        else if (D > lo) m = (1u << (D - lo)) - 1u;
        s_amask[j] = m;
    }
    __syncthreads();

    // ---- prologue: argmin for merge 0
    {
        float v0 = s_vals[e0], v1 = s_vals[e1];
        float v; int bi;
        if (v1 < v0) { v = v1; bi = e1; } else { v = v0; bi = e0; }  // leftmost on tie
        #pragma unroll
        for (int o = 16; o; o >>= 1) {
            float ov = __shfl_down_sync(~0u, v, o);
            int oi = __shfl_down_sync(~0u, bi, o);
            if (ov < v || (ov == v && oi < bi)) { v = ov; bi = oi; }
        }
        if (lane == 0) { s_pv[wid] = v; s_pi[wid] = bi; }
    }
    __syncthreads();
    if (j == 0) {
        float bv = s_pv[0]; int b = s_pi[0];
        #pragma unroll
        for (int w = 1; w < 16; w++) {
            float wv = s_pv[w]; int wi = s_pi[w];
            if (wv < bv || (wv == bv && wi < b)) { bv = wv; b = wi; }
        }
        int m1 = b, m2 = s_idx[b];
        s_m1 = m1; s_m2 = m2;
        float c1 = s_cs[m1], c2 = s_cs[m2];
        float ncs = __fadd_rn(c1, c2);
        s_cs1 = c1; s_cs2 = c2; s_ncs = ncs;
        s_cs[m1] = ncs;
        s_vals[m2] = MAXD;
        s_amask[m2 >> 5] &= ~(1u << (m2 & 31));
        s_nresc = 0;
    }
    __syncthreads();

    int take_prev = 0, cntA_prev = 0, cntB_prev = 0;

    for (int it = 0; it < D - 1; ++it) {
        const int m1 = s_m1, m2 = s_m2;
        const float cs1 = s_cs1, cs2 = s_cs2, ncs = s_ncs;

        // ==== Region1: ballots + dist loads (issue early), R-writes(prev), maintenance
        int mem0 = (e0 < D) ? s_member[e0] : -1;
        int mem1 = (e1 < D) ? s_member[e1] : -1;
        unsigned balA0 = __ballot_sync(~0u, mem0 == m1);
        unsigned balA1 = __ballot_sync(~0u, mem1 == m1);
        unsigned balB0 = __ballot_sync(~0u, mem0 == m2);
        unsigned balB1 = __ballot_sync(~0u, mem1 == m2);
        if (lane == 0) {
            s_wcA[wid] = __popc(balA0) + __popc(balA1);
            s_wcB[wid] = __popc(balB0) + __popc(balB1);
        }
        if (mem0 == m2) s_member[e0] = m1;
        if (mem1 == m2) s_member[e1] = m1;

        float d10 = MAXD, d11 = MAXD, d20 = MAXD, d21 = MAXD;
        if (e0 < D) {
            if (evenD && e1 < D) {
                float2 t1 = *(const float2*)&g_Dm[(size_t)m1 * D + e0];
                float2 t2 = *(const float2*)&g_Dm[(size_t)m2 * D + e0];
                d10 = t1.x; d11 = t1.y; d20 = t2.x; d21 = t2.y;
            } else {
                d10 = g_Dm[(size_t)m1 * D + e0];
                d20 = g_Dm[(size_t)m2 * D + e0];
                if (e1 < D) { d11 = g_Dm[(size_t)m1 * D + e1]; d21 = g_Dm[(size_t)m2 * D + e1]; }
            }
        }

        // R-writes for previous merge (overlaps the load latency above)
        if (take_prev) {
            int cnt = cntA_prev + cntB_prev;
            for (int ai = wid; ai < cnt; ai += 16) {
                int a = (ai < cntA_prev) ? s_list[ai] : s_list[MAXDIM - 1 - (ai - cntA_prev)];
                float* rp = R + (size_t)a * D;
                for (int b2 = lane; b2 < cnt; b2 += 32) {
                    int b = (b2 < cntA_prev) ? s_list[b2] : s_list[MAXDIM - 1 - (b2 - cntA_prev)];
                    rp[b] = 1.0f;
                }
            }
        }

        // distance update + incremental min maintenance, per owned element
        {
            int alive0 = (e0 < D) && ((s_amask[e0 >> 5] >> (e0 & 31)) & 1);
            int alive1 = (e1 < D) && ((s_amask[e1 >> 5] >> (e1 & 31)) & 1);
            float nv0 = MAXD, nv1 = MAXD;
            int need0 = 0, need1 = 0;
            if (alive0) {
                if (e0 != m1) {
                    nv0 = __fdiv_rn(__fadd_rn(__fmul_rn(d10, cs1), __fmul_rn(d20, cs2)), ncs);
                    float vold = s_vals[e0]; int iold = s_idx[e0];
                    if (iold == m2) need0 = 1;
                    else if (m1 > e0) {
                        if (iold == m1) {
                            if (nv0 <= vold) s_vals[e0] = nv0; else need0 = 1;
                        } else {
                            if (nv0 < vold) { s_vals[e0] = nv0; s_idx[e0] = m1; }
                            else if (nv0 == vold && m1 < iold) s_idx[e0] = m1;
                        }
                    }
                } else need0 = 1;
            }
            if (alive1) {
                if (e1 != m1) {
                    nv1 = __fdiv_rn(__fadd_rn(__fmul_rn(d11, cs1), __fmul_rn(d21, cs2)), ncs);
                    float vold = s_vals[e1]; int iold = s_idx[e1];
                    if (iold == m2) need1 = 1;
                    else if (m1 > e1) {
                        if (iold == m1) {
                            if (nv1 <= vold) s_vals[e1] = nv1; else need1 = 1;
                        } else {
                            if (nv1 < vold) { s_vals[e1] = nv1; s_idx[e1] = m1; }
                            else if (nv1 == vold && m1 < iold) s_idx[e1] = m1;
                        }
                    }
                } else need1 = 1;
            }
            if (e0 < D) {
                if (evenD && e1 < D) {
                    float2 t; t.x = nv0; t.y = nv1;
                    *(float2*)&g_Dm[(size_t)m1 * D + e0] = t;
                } else {
                    g_Dm[(size_t)m1 * D + e0] = nv0;
                    if (e1 < D) g_Dm[(size_t)m1 * D + e1] = nv1;
                }
            }
            if (alive0) g_Dm[(size_t)e0 * D + m1] = nv0;
            if (alive1) g_Dm[(size_t)e1 * D + m1] = nv1;
            if (need0) { int p = atomicAdd(&s_nresc, 1); s_rlist[p] = e0; }
            if (need1) { int p = atomicAdd(&s_nresc, 1); s_rlist[p] = e1; }
        }
        __syncthreads();

        // ==== Region2: stable list compaction + rescans
        int cntA, cntB;
        {
            int ca = (lane < 16) ? s_wcA[lane] : 0;
            int cb = (lane < 16) ? s_wcB[lane] : 0;
            #pragma unroll
            for (int o = 1; o < 32; o <<= 1) {
                int t = __shfl_up_sync(~0u, ca, o); if (lane >= o) ca += t;
                t = __shfl_up_sync(~0u, cb, o); if (lane >= o) cb += t;
            }
            cntA = __shfl_sync(~0u, ca, 15);
            cntB = __shfl_sync(~0u, cb, 15);
            int offA = __shfl_sync(~0u, ca, wid) - s_wcA[wid];
            int offB = __shfl_sync(~0u, cb, wid) - s_wcB[wid];
            int w0A = __popc(balA0 & lml) + __popc(balA1 & lml);
            int w0B = __popc(balB0 & lml) + __popc(balB1 & lml);
            if (mem0 == m1) s_list[offA + w0A] = e0;
            if (mem1 == m1) s_list[offA + w0A + (mem0 == m1 ? 1 : 0)] = e1;
            if (mem0 == m2) s_list[MAXDIM - 1 - (offB + w0B)] = e0;
            if (mem1 == m2) s_list[MAXDIM - 1 - (offB + w0B + (mem0 == m2 ? 1 : 0))] = e1;
        }
        {
            int nr = s_nresc;
            for (int t = wid; t < nr; t += 16) {
                int r = s_rlist[t];
                float bv = MAXD; int bbi = 0;
                if (vec4) {
                    const float4* row4 = reinterpret_cast<const float4*>(&g_Dm[(size_t)r * D]);
                    float4 q[8];
                    #pragma unroll
                    for (int c = 0; c < 8; c++) {
                        int k = c * 128 + lane * 4;
                        if (k < D) q[c] = row4[k >> 2];
                        else { q[c].x = MAXD; q[c].y = MAXD; q[c].z = MAXD; q[c].w = MAXD; }
                    }
                    #pragma unroll
                    for (int c = 0; c < 8; c++) {
                        int k = c * 128 + lane * 4;
                        unsigned am = (k < D) ? (s_amask[k >> 5] >> (k & 31)) : 0u;
                        float f0 = ((am & 1u) && k > r)       ? q[c].x : MAXD;
                        float f1 = ((am & 2u) && (k + 1) > r) ? q[c].y : MAXD;
                        float f2 = ((am & 4u) && (k + 2) > r) ? q[c].z : MAXD;
                        float f3 = ((am & 8u) && (k + 3) > r) ? q[c].w : MAXD;
                        if (f0 < bv) { bv = f0; bbi = k; }
                        if (f1 < bv) { bv = f1; bbi = k + 1; }
                        if (f2 < bv) { bv = f2; bbi = k + 2; }
                        if (f3 < bv) { bv = f3; bbi = k + 3; }
                    }
                } else {
                    const float* row = &g_Dm[(size_t)r * D];
                    for (int k = lane; k < D; k += 32) {
                        int alv = (s_amask[k >> 5] >> (k & 31)) & 1;
                        float vv = (alv && k > r) ? row[k] : MAXD;
                        if (vv < bv) { bv = vv; bbi = k; }
                    }
                }
                #pragma unroll
                for (int o = 16; o; o >>= 1) {
                    float ov = __shfl_down_sync(~0u, bv, o);
                    int oi = __shfl_down_sync(~0u, bbi, o);
                    if (ov < bv || (ov == bv && oi < bbi)) { bv = ov; bbi = oi; }
                }
                if (lane == 0) { s_vals[r] = bv; s_idx[r] = bbi; }
            }
        }
        __syncthreads();

        // ==== Region3: next-merge argmin pre-reduce + cross-energy pair sum
        {
            float v0 = s_vals[e0], v1 = s_vals[e1];
            float v; int bi;
            if (v1 < v0) { v = v1; bi = e1; } else { v = v0; bi = e0; }
            #pragma unroll
            for (int o = 16; o; o >>= 1) {
                float ov = __shfl_down_sync(~0u, v, o);
                int oi = __shfl_down_sync(~0u, bi, o);
                if (ov < v || (ov == v && oi < bi)) { v = ov; bi = oi; }
            }
            if (lane == 0) { s_pv[wid] = v; s_pi[wid] = bi; }
        }
        {
            float ps = 0.f;
            for (int ia = wid; ia < cntA; ia += 16) {
                int a = s_list[ia];
                for (int ib = lane; ib < cntB; ib += 32) {
                    int b = s_list[MAXDIM - 1 - ib];
                    int lo = a < b ? a : b, hi = a < b ? b : a;
                    ps = __fadd_rn(ps, __ldg(&W[(size_t)lo * D + hi]));
                }
            }
            #pragma unroll
            for (int o = 16; o; o >>= 1) ps = __fadd_rn(ps, __shfl_down_sync(~0u, ps, o));
            if (lane == 0) s_pw[wid] = ps;
        }
        __syncthreads();

        // ==== Region4 (thread 0): take decision + next-merge sequencing
        if (j == 0) {
            float cross = 0.f;
            #pragma unroll
            for (int w = 0; w < 16; w++) cross = __fadd_rn(cross, s_pw[w]);
            float me = __fadd_rn(__fadd_rn(s_within[m1], s_within[m2]), cross);
            float es = __fadd_rn(s_energy[m1], s_energy[m2]);
            int take = (me >= es) ? 1 : 0;
            s_take = take;
            s_within[m1] = me;
            s_energy[m1] = take ? me : es;
            // next merge selection (garbage on last iteration — unused)
            float bv = s_pv[0]; int b = s_pi[0];
            #pragma unroll
            for (int w = 1; w < 16; w++) {
                float wv = s_pv[w]; int wi = s_pi[w];
                if (wv < bv || (wv == bv && wi < b)) { bv = wv; b = wi; }
            }
            int n1 = b, n2 = s_idx[b];
            s_m1 = n1; s_m2 = n2;
            float c1 = s_cs[n1], c2 = s_cs[n2];
            float nncs = __fadd_rn(c1, c2);
            s_cs1 = c1; s_cs2 = c2; s_ncs = nncs;
            s_cs[n1] = nncs;
            s_vals[n2] = MAXD;
            s_amask[n2 >> 5] &= ~(1u << (n2 & 31));
            s_nresc = 0;
        }
        __syncthreads();

        take_prev = s_take; cntA_prev = cntA; cntB_prev = cntB;
    }

    // ==== epilogue: R-writes for the final merge
    if (take_prev) {
        int cnt = cntA_prev + cntB_prev;
        for (int ai = wid; ai < cnt; ai += 16) {
            int a = (ai < cntA_prev) ? s_list[ai] : s_list[MAXDIM - 1 - (ai - cntA_prev)];
            float* rp = R + (size_t)a * D;
            for (int b2 = lane; b2 < cnt; b2 += 32) {
                int b = (b2 < cntA_prev) ? s_list[b2] : s_list[MAXDIM - 1 - (b2 - cntA_prev)];
                rp[b] = 1.0f;
            }
        }
    }
}

extern "C" void kernel_launch(void* const* d_in, const int* in_sizes, int n_in,
                              void* d_out, int out_size) {
    const float* X = (const float*)d_in[0];
    const float* W = (const float*)d_in[1];
    float* R = (float*)d_out;
    int n = in_sizes[0];
    int D = (int)(sqrt((double)n) + 0.5);
    if (D < 2 || D > MAXDIM) return;

    k_reset<<<1, 1>>>();
    k_maxred<<<256, 256>>>(X, n);
    k_init<<<D, 256>>>(X, R, D);
    k_hac<<<1, NT>>>(W, R, D);
}